// round 10
// baseline (speedup 1.0000x reference)
#include <cuda_runtime.h>
#include <cuda_bf16.h>
#include <cstdint>
#include <cstddef>
#include <math.h>

#define NB   32      // batch
#define T1   2000
#define T2   1000
#define D1   80
#define HH   256     // hidden per direction
#define G4H  1024    // 4*H gate rows
#define HDC  512
#define OUTC 512
#define CLSZ 16      // cluster size = blocks per group (h-shards)

typedef unsigned long long ull;

// ---------------- f32x2 packed-FMA helpers (Blackwell FFMA2) -----------------
__device__ __forceinline__ void fma2(ull& d, ull a, ull b) {
    asm("fma.rn.f32x2 %0, %1, %2, %3;" : "=l"(d) : "l"(a), "l"(b), "l"(d));
}
__device__ __forceinline__ ull dup2(float x) {
    ull r; asm("mov.b64 %0, {%1, %1};" : "=l"(r) : "f"(x)); return r;
}
__device__ __forceinline__ float2 unp2(ull v) {
    float2 r; asm("mov.b64 {%0, %1}, %2;" : "=f"(r.x), "=f"(r.y) : "l"(v)); return r;
}
__device__ __forceinline__ uint32_t smem_u32(const void* p) {
    uint32_t a;
    asm("{ .reg .u64 t; cvta.to.shared.u64 t, %1; cvt.u32.u64 %0, t; }" : "=r"(a) : "l"(p));
    return a;
}
__device__ __forceinline__ uint32_t mapa_u32(uint32_t addr, int rank) {
    uint32_t r;
    asm("mapa.shared::cluster.u32 %0, %1, %2;" : "=r"(r) : "r"(addr), "r"(rank));
    return r;
}

// ---------------- device scratch ---------------------------------------------
__device__ float g_xg1f[(size_t)T1 * G4H * NB];   // [t][gate_row][b]
__device__ float g_xg1b[(size_t)T1 * G4H * NB];
__device__ float g_xg2f[(size_t)T2 * G4H * NB];
__device__ float g_xg2b[(size_t)T2 * G4H * NB];
__device__ float g_out1[(size_t)NB * T1 * HDC];   // [b][t][ch]
__device__ float g_pool1[(size_t)NB * T2 * HDC];
__device__ float g_out2[(size_t)NB * T2 * HDC];

// ---------------- small helpers ---------------------------------------------
__global__ void k_zero(float* __restrict__ p, size_t n) {
    size_t i = (size_t)blockIdx.x * blockDim.x + threadIdx.x;
    size_t st = (size_t)gridDim.x * blockDim.x;
    for (; i < n; i += st) p[i] = 0.f;
}

__global__ void k_pool(const float* __restrict__ in, float* __restrict__ out) {
    size_t n = (size_t)NB * T2 * HDC;
    size_t i = (size_t)blockIdx.x * blockDim.x + threadIdx.x;
    size_t st = (size_t)gridDim.x * blockDim.x;
    for (; i < n; i += st) {
        int c  = (int)(i % HDC);
        size_t r = i / HDC;
        int tp = (int)(r % T2);
        int b  = (int)(r / T2);
        const float* p = in + ((size_t)b * T1 + 2 * (size_t)tp) * HDC + c;
        out[i] = fmaxf(p[0], p[HDC]);
    }
}

__global__ void k_lens(const int* __restrict__ xlen, float* __restrict__ out) {
    int i = threadIdx.x;
    if (i < NB) out[i] = (float)(xlen[i] >> 1);
}

// ---------------- projection / linear GEMM (pipelined double-buffer) ---------
// C[row][b] at time t: bias[row] + sum_k W[row][k] * X[(b*Tt+t)*K + k]
// Block tile: 256 rows x (one t x 32 b). 128 threads, thread tile 8 rows x 8 b.
// K chunks of 16 are software-pipelined: chunk c+1 LDGs fly during chunk c math.
__global__ void __launch_bounds__(128, 2) k_proj(
    const float* __restrict__ X, const float* __restrict__ W,
    const float* __restrict__ bias, float* __restrict__ out,
    int Tt, int K, long long ot, long long orr, long long ob)
{
    __shared__ __align__(16) float a_sh[2][16][256];   // [buf][k][row]
    __shared__ __align__(16) ull   b2sh[2][16][32];    // [buf][k][b]  pre-dup'd

    const int t    = blockIdx.y;
    const int row0 = blockIdx.x * 256;
    const int tid  = threadIdx.x;
    const int rowg = tid >> 2;   // 0..31 -> rows rowg*8 .. +7
    const int colg = tid & 3;    // 0..3  -> b colg*8 .. +7

    // staging roles
    const int xbb = tid >> 2;          // batch for X stage
    const int xko = (tid & 3) * 4;     // k offset for X stage
    const float* wp_base = W + (size_t)(row0 + tid) * K;
    const float* xp_base = X + ((size_t)xbb * Tt + t) * K + xko;

    ull acc[4][8];
#pragma unroll
    for (int i = 0; i < 4; i++)
#pragma unroll
        for (int j = 0; j < 8; j++) acc[i][j] = 0ull;

    const int nc = K >> 4;   // chunks of 16 (K % 16 == 0 at all call sites)

    // in-flight registers
    float4 w0, w1, w2, w3, w4, w5, w6, w7;
    float4 xv;

    // prologue: load chunk 0
    {
        const float* wp = wp_base;
        w0 = ((const float4*)wp)[0]; w1 = ((const float4*)wp)[1];
        w2 = ((const float4*)wp)[2]; w3 = ((const float4*)wp)[3];
        wp += (size_t)128 * K;
        w4 = ((const float4*)wp)[0]; w5 = ((const float4*)wp)[1];
        w6 = ((const float4*)wp)[2]; w7 = ((const float4*)wp)[3];
        xv = *(const float4*)xp_base;
    }

    for (int c = 0; c < nc; c++) {
        const int buf = c & 1;
        // ---- store staged regs into buf ----
        {
            float* a0 = &a_sh[buf][0][tid];
            a0[0*256] = w0.x; a0[1*256] = w0.y; a0[2*256] = w0.z; a0[3*256] = w0.w;
            a0[4*256] = w1.x; a0[5*256] = w1.y; a0[6*256] = w1.z; a0[7*256] = w1.w;
            a0[8*256] = w2.x; a0[9*256] = w2.y; a0[10*256] = w2.z; a0[11*256] = w2.w;
            a0[12*256] = w3.x; a0[13*256] = w3.y; a0[14*256] = w3.z; a0[15*256] = w3.w;
            float* a1 = &a_sh[buf][0][tid + 128];
            a1[0*256] = w4.x; a1[1*256] = w4.y; a1[2*256] = w4.z; a1[3*256] = w4.w;
            a1[4*256] = w5.x; a1[5*256] = w5.y; a1[6*256] = w5.z; a1[7*256] = w5.w;
            a1[8*256] = w6.x; a1[9*256] = w6.y; a1[10*256] = w6.z; a1[11*256] = w6.w;
            a1[12*256] = w7.x; a1[13*256] = w7.y; a1[14*256] = w7.z; a1[15*256] = w7.w;
            b2sh[buf][xko + 0][xbb] = dup2(xv.x);
            b2sh[buf][xko + 1][xbb] = dup2(xv.y);
            b2sh[buf][xko + 2][xbb] = dup2(xv.z);
            b2sh[buf][xko + 3][xbb] = dup2(xv.w);
        }
        __syncthreads();

        // ---- issue LDGs for chunk c+1 (fly under the math) ----
        if (c + 1 < nc) {
            const int k0n = (c + 1) * 16;
            const float* wp = wp_base + k0n;
            w0 = ((const float4*)wp)[0]; w1 = ((const float4*)wp)[1];
            w2 = ((const float4*)wp)[2]; w3 = ((const float4*)wp)[3];
            wp += (size_t)128 * K;
            w4 = ((const float4*)wp)[0]; w5 = ((const float4*)wp)[1];
            w6 = ((const float4*)wp)[2]; w7 = ((const float4*)wp)[3];
            xv = *(const float4*)(xp_base + k0n);
        }

        // ---- math over buf ----
#pragma unroll
        for (int kk = 0; kk < 16; kk++) {
            ulonglong2 a01 = *(const ulonglong2*)&a_sh[buf][kk][rowg * 8];
            ulonglong2 a23 = *(const ulonglong2*)&a_sh[buf][kk][rowg * 8 + 4];
            ulonglong2 p01 = *(const ulonglong2*)&b2sh[buf][kk][colg * 8];
            ulonglong2 p23 = *(const ulonglong2*)&b2sh[buf][kk][colg * 8 + 2];
            ulonglong2 p45 = *(const ulonglong2*)&b2sh[buf][kk][colg * 8 + 4];
            ulonglong2 p67 = *(const ulonglong2*)&b2sh[buf][kk][colg * 8 + 6];
            fma2(acc[0][0], a01.x, p01.x); fma2(acc[0][1], a01.x, p01.y);
            fma2(acc[0][2], a01.x, p23.x); fma2(acc[0][3], a01.x, p23.y);
            fma2(acc[0][4], a01.x, p45.x); fma2(acc[0][5], a01.x, p45.y);
            fma2(acc[0][6], a01.x, p67.x); fma2(acc[0][7], a01.x, p67.y);
            fma2(acc[1][0], a01.y, p01.x); fma2(acc[1][1], a01.y, p01.y);
            fma2(acc[1][2], a01.y, p23.x); fma2(acc[1][3], a01.y, p23.y);
            fma2(acc[1][4], a01.y, p45.x); fma2(acc[1][5], a01.y, p45.y);
            fma2(acc[1][6], a01.y, p67.x); fma2(acc[1][7], a01.y, p67.y);
            fma2(acc[2][0], a23.x, p01.x); fma2(acc[2][1], a23.x, p01.y);
            fma2(acc[2][2], a23.x, p23.x); fma2(acc[2][3], a23.x, p23.y);
            fma2(acc[2][4], a23.x, p45.x); fma2(acc[2][5], a23.x, p45.y);
            fma2(acc[2][6], a23.x, p67.x); fma2(acc[2][7], a23.x, p67.y);
            fma2(acc[3][0], a23.y, p01.x); fma2(acc[3][1], a23.y, p01.y);
            fma2(acc[3][2], a23.y, p23.x); fma2(acc[3][3], a23.y, p23.y);
            fma2(acc[3][4], a23.y, p45.x); fma2(acc[3][5], a23.y, p45.y);
            fma2(acc[3][6], a23.y, p67.x); fma2(acc[3][7], a23.y, p67.y);
        }
        // no trailing sync: next iter writes buf^1 (not being read);
        // the sync at the top of the next iter guards reads of buf^1.
    }

    // ---- epilogue ----
    const int rbase = row0 + rowg * 8;
    float4 bv0 = *(const float4*)&bias[rbase];
    float4 bv1 = *(const float4*)&bias[rbase + 4];
    const float bv[8] = {bv0.x, bv0.y, bv0.z, bv0.w, bv1.x, bv1.y, bv1.z, bv1.w};

    if (ob == 1) {
        float* op = out + (size_t)t * ot + (size_t)rbase * orr + colg * 8;
#pragma unroll
        for (int rp = 0; rp < 4; rp++) {
            float va[8], vb[8];
#pragma unroll
            for (int cc = 0; cc < 8; cc++) {
                float2 u = unp2(acc[rp][cc]);
                va[cc] = u.x + bv[2 * rp];
                vb[cc] = u.y + bv[2 * rp + 1];
            }
            float* r0 = op + (size_t)(2 * rp) * orr;
            float* r1 = op + (size_t)(2 * rp + 1) * orr;
            *(float4*)r0       = make_float4(va[0], va[1], va[2], va[3]);
            *(float4*)(r0 + 4) = make_float4(va[4], va[5], va[6], va[7]);
            *(float4*)r1       = make_float4(vb[0], vb[1], vb[2], vb[3]);
            *(float4*)(r1 + 4) = make_float4(vb[4], vb[5], vb[6], vb[7]);
        }
    } else {
        float* op = out + (size_t)t * ot + rbase;
#pragma unroll
        for (int cc = 0; cc < 8; cc++) {
            size_t boff = (size_t)(colg * 8 + cc) * ob;
            float2 p0 = unp2(acc[0][cc]);
            float2 p1 = unp2(acc[1][cc]);
            float2 p2 = unp2(acc[2][cc]);
            float2 p3 = unp2(acc[3][cc]);
            *(float4*)(op + boff)     = make_float4(p0.x + bv[0], p0.y + bv[1], p1.x + bv[2], p1.y + bv[3]);
            *(float4*)(op + boff + 4) = make_float4(p2.x + bv[4], p2.y + bv[5], p3.x + bv[6], p3.y + bv[7]);
        }
    }
}

// ---------------- persistent recurrent LSTM: DSMEM cluster groups (frozen R9)-
__device__ __forceinline__ float fsig(float x) {
    return 1.f / (1.f + __expf(-x));
}
__device__ __forceinline__ float ftanh(float x) {
    float e = __expf(2.f * x);
    return 1.f - 2.f / (e + 1.f);
}

#define PART_STRIDE 9
#define HBUF_FLOATS (HH * 8)
#define LSTM_SMEM (65536 + 2 * HBUF_FLOATS * 4 + 4 * 64 * PART_STRIDE * 4)

__global__ void __launch_bounds__(128, 1) k_lstm(
    const float* __restrict__ xgF, const float* __restrict__ xgB,
    const float* __restrict__ WhhF, const float* __restrict__ WhhB,
    const int* __restrict__ xlen, int lenShift,
    float* __restrict__ out, int Tt)
{
    extern __shared__ __align__(16) char dynsmem[];
    float* w_sh = (float*)dynsmem;                       // [256][64]
    float* h_sh = (float*)(dynsmem + 65536);             // [2][256][8]
    float* part = (float*)(dynsmem + 65536 + 2 * HBUF_FLOATS * 4);

    const int bx  = (int)blockIdx.x;
    const int dir = bx >> 6;
    const int bs  = (bx >> 4) & 3;
    const int hs  = bx & 15;           // cluster rank

    const float* xg  = dir ? xgB : xgF;
    const float* Whh = dir ? WhhB : WhhF;

    const int tid  = threadIdx.x;
    const int warp = tid >> 5, lane = tid & 31;
    const int q    = lane & 15;
    const int bg4  = lane >> 4;
    const int kbase = warp * 64;

    {
        float4* hz = (float4*)h_sh;
#pragma unroll
        for (int j = tid; j < 2 * HBUF_FLOATS / 4; j += 128) hz[j] = make_float4(0.f, 0.f, 0.f, 0.f);
    }

    {
        const int r  = tid & 63;
        const int ko = (tid >> 6) * 128;
        const int grow = (r >> 4) * HH + hs * 16 + (r & 15);
        const float* wp = Whh + (size_t)grow * HH + ko;
#pragma unroll
        for (int j = 0; j < 128; j += 4) {
            float4 v = *(const float4*)(wp + j);
            w_sh[(size_t)(ko + j + 0) * 64 + r] = v.x;
            w_sh[(size_t)(ko + j + 1) * 64 + r] = v.y;
            w_sh[(size_t)(ko + j + 2) * 64 + r] = v.z;
            w_sh[(size_t)(ko + j + 3) * 64 + r] = v.w;
        }
    }

    const uint32_t h_u32 = smem_u32(h_sh);
    uint32_t peer[CLSZ];
#pragma unroll
    for (int r = 0; r < CLSZ; r++) peer[r] = mapa_u32(h_u32, r);
    const uint32_t selfOff = ((uint32_t)(hs * 128 + tid)) * 4u;

    const int hl_p = tid >> 3;
    const int bl_p = tid & 7;
    const int hk   = hs * 16 + hl_p;
    const int b_g  = bs * 8 + bl_p;
    const int len_b = xlen[b_g] >> lenShift;
    int gmax = 0;
#pragma unroll
    for (int j = 0; j < 8; j++) {
        int l = xlen[bs * 8 + j] >> lenShift;
        gmax = (l > gmax) ? l : gmax;
    }
    float c_st = 0.f, h_st = 0.f;

    __syncthreads();
    asm volatile("barrier.cluster.arrive.aligned;" ::: "memory");
    asm volatile("barrier.cluster.wait.aligned;" ::: "memory");

    float xg0, xg1, xg2, xg3;
    {
        int tx = dir ? (len_b - 1) : 0;
        if (tx < 0) tx = 0;
        const float* xp = xg + (size_t)tx * (G4H * NB) + (size_t)hk * NB + b_g;
        xg0 = __ldg(xp);
        xg1 = __ldg(xp + 256 * NB);
        xg2 = __ldg(xp + 512 * NB);
        xg3 = __ldg(xp + 768 * NB);
    }

    for (int s = 0; s < gmax; s++) {
        const int bufp = s & 1;

        ull acc[2][4] = {};
        const float* wq = w_sh + (size_t)kbase * 64 + q * 4;
        const float* hq = h_sh + (size_t)bufp * HBUF_FLOATS + (size_t)kbase * 8 + bg4 * 4;
#pragma unroll 16
        for (int k = 0; k < 64; k++) {
            ulonglong2 wv = *(const ulonglong2*)(wq + (size_t)k * 64);
            float4 hv = *(const float4*)(hq + (size_t)k * 8);
            ull h0 = dup2(hv.x), h1 = dup2(hv.y), h2 = dup2(hv.z), h3 = dup2(hv.w);
            fma2(acc[0][0], wv.x, h0); fma2(acc[0][1], wv.x, h1);
            fma2(acc[0][2], wv.x, h2); fma2(acc[0][3], wv.x, h3);
            fma2(acc[1][0], wv.y, h0); fma2(acc[1][1], wv.y, h1);
            fma2(acc[1][2], wv.y, h2); fma2(acc[1][3], wv.y, h3);
        }

#pragma unroll
        for (int i = 0; i < 2; i++) {
#pragma unroll
            for (int j = 0; j < 4; j++) {
                float2 u = unp2(acc[i][j]);
                float* p0 = part + ((size_t)warp * 64 + q * 4 + 2 * i) * PART_STRIDE + bg4 * 4 + j;
                p0[0] = u.x;
                p0[PART_STRIDE] = u.y;
            }
        }
        __syncthreads();

        float g0 = xg0, g1 = xg1, g2 = xg2, g3 = xg3;
#pragma unroll
        for (int w = 0; w < 4; w++) {
            const float* pr = part + (size_t)w * 64 * PART_STRIDE + bl_p;
            g0 += pr[(0  + hl_p) * PART_STRIDE];
            g1 += pr[(16 + hl_p) * PART_STRIDE];
            g2 += pr[(32 + hl_p) * PART_STRIDE];
            g3 += pr[(48 + hl_p) * PART_STRIDE];
        }
        float ig = fsig(g0);
        float fg = fsig(g1);
        float gg = ftanh(g2);
        float og = fsig(g3);
        float c_n = fg * c_st + ig * gg;
        float h_n = og * ftanh(c_n);
        if (s < len_b) {
            c_st = c_n; h_st = h_n;
            int t_o = dir ? (len_b - 1 - s) : s;
            out[((size_t)b_g * Tt + t_o) * HDC + dir * HH + hk] = h_n;
        }

        {
            const uint32_t off = (uint32_t)((bufp ^ 1) * HBUF_FLOATS * 4) + selfOff;
            const float hv = h_st;
#pragma unroll
            for (int r = 0; r < CLSZ; r++) {
                asm volatile("st.shared::cluster.f32 [%0], %1;"
                             :: "r"(peer[r] + off), "f"(hv) : "memory");
            }
        }

        asm volatile("barrier.cluster.arrive.aligned;" ::: "memory");
        {
            int sn = s + 1;
            int tx = dir ? (len_b - 1 - sn) : sn;
            if (tx < 0) tx = 0;
            if (tx >= Tt) tx = Tt - 1;
            const float* xp = xg + (size_t)tx * (G4H * NB) + (size_t)hk * NB + b_g;
            xg0 = __ldg(xp);
            xg1 = __ldg(xp + 256 * NB);
            xg2 = __ldg(xp + 512 * NB);
            xg3 = __ldg(xp + 768 * NB);
        }
        asm volatile("barrier.cluster.wait.aligned;" ::: "memory");
    }
}

// ---------------- host orchestration ----------------------------------------
extern "C" void kernel_launch(void* const* d_in, const int* in_sizes, int n_in,
                              void* d_out, int out_size) {
    const float* x     = (const float*)d_in[0];
    const int*   xlen  = (const int*)d_in[1];
    const float* Wih1f = (const float*)d_in[2];
    const float* Whh1f = (const float*)d_in[3];
    const float* b1f   = (const float*)d_in[4];
    const float* Wih1b = (const float*)d_in[5];
    const float* Whh1b = (const float*)d_in[6];
    const float* b1b   = (const float*)d_in[7];
    const float* Wih2f = (const float*)d_in[8];
    const float* Whh2f = (const float*)d_in[9];
    const float* b2f   = (const float*)d_in[10];
    const float* Wih2b = (const float*)d_in[11];
    const float* Whh2b = (const float*)d_in[12];
    const float* b2b   = (const float*)d_in[13];
    const float* Wlin  = (const float*)d_in[14];
    const float* blin  = (const float*)d_in[15];
    float* out = (float*)d_out;

    static bool s_attr_done = false;
    if (!s_attr_done) {
        cudaFuncSetAttribute(k_lstm, cudaFuncAttributeMaxDynamicSharedMemorySize, LSTM_SMEM);
        cudaFuncSetAttribute(k_lstm, cudaFuncAttributeNonPortableClusterSizeAllowed, 1);
        s_attr_done = true;
    }

    float *xg1f, *xg1b, *xg2f, *xg2b, *out1, *pool1, *out2;
    cudaGetSymbolAddress((void**)&xg1f,  g_xg1f);
    cudaGetSymbolAddress((void**)&xg1b,  g_xg1b);
    cudaGetSymbolAddress((void**)&xg2f,  g_xg2f);
    cudaGetSymbolAddress((void**)&xg2b,  g_xg2b);
    cudaGetSymbolAddress((void**)&out1,  g_out1);
    cudaGetSymbolAddress((void**)&pool1, g_pool1);
    cudaGetSymbolAddress((void**)&out2,  g_out2);

    const long long ot_xg = (long long)G4H * NB;
    const long long or_xg = NB;
    const long long ob_xg = 1;

    // zero masked-output buffers (graph replays must rewrite every call)
    k_zero<<<4096, 256>>>(out1, (size_t)NB * T1 * HDC);
    k_zero<<<4096, 256>>>(out2, (size_t)NB * T2 * HDC);

    // layer-1 gate projections: M=1024, N=(2000 t x 32 b), K=80
    k_proj<<<dim3(G4H / 256, T1), 128>>>(x, Wih1f, b1f, xg1f, T1, D1, ot_xg, or_xg, ob_xg);
    k_proj<<<dim3(G4H / 256, T1), 128>>>(x, Wih1b, b1b, xg1b, T1, D1, ot_xg, or_xg, ob_xg);

    // cluster launch helper
    auto launch_lstm = [&](const float* xf, const float* xb,
                           const float* wf, const float* wb,
                           int shift, float* o, int Tt) {
        cudaLaunchConfig_t cfg = {};
        cfg.gridDim  = dim3(128, 1, 1);
        cfg.blockDim = dim3(128, 1, 1);
        cfg.dynamicSmemBytes = LSTM_SMEM;
        cfg.stream = 0;
        cudaLaunchAttribute attrs[1];
        attrs[0].id = cudaLaunchAttributeClusterDimension;
        attrs[0].val.clusterDim.x = CLSZ;
        attrs[0].val.clusterDim.y = 1;
        attrs[0].val.clusterDim.z = 1;
        cfg.attrs = attrs;
        cfg.numAttrs = 1;
        cudaLaunchKernelEx(&cfg, k_lstm, xf, xb, wf, wb, xlen, shift, o, Tt);
    };

    // layer-1 recurrence
    launch_lstm(xg1f, xg1b, Whh1f, Whh1b, 0, out1, T1);

    // max-pool stride 2
    k_pool<<<2048, 256>>>(out1, pool1);

    // layer-2 gate projections: M=1024, K=512
    k_proj<<<dim3(G4H / 256, T2), 128>>>(pool1, Wih2f, b2f, xg2f, T2, HDC, ot_xg, or_xg, ob_xg);
    k_proj<<<dim3(G4H / 256, T2), 128>>>(pool1, Wih2b, b2b, xg2b, T2, HDC, ot_xg, or_xg, ob_xg);

    // layer-2 recurrence (lengths = x_len >> 1)
    launch_lstm(xg2f, xg2b, Whh2f, Whh2b, 1, out2, T2);

    // final linear: out[b][t][o] -> M=512, K=512, store-along-row mode
    k_proj<<<dim3(OUTC / 256, T2), 128>>>(out2, Wlin, blin, out, T2, HDC,
                                          (long long)OUTC, 1LL, (long long)T2 * OUTC);

    // lens = x_len // 2 appended as float
    if (out_size > NB * T2 * OUTC) {
        k_lens<<<1, 32>>>(xlen, out + (size_t)NB * T2 * OUTC);
    }
}

// round 11
// speedup vs baseline: 1.0060x; 1.0060x over previous
#include <cuda_runtime.h>
#include <cuda_bf16.h>
#include <cstdint>
#include <cstddef>
#include <math.h>

#define NB   32      // batch
#define T1   2000
#define T2   1000
#define D1   80
#define HH   256     // hidden per direction
#define G4H  1024    // 4*H gate rows
#define HDC  512
#define OUTC 512
#define CLSZ 16      // cluster size = blocks per group (h-shards)

typedef unsigned long long ull;

// ---------------- f32x2 packed-FMA helpers (Blackwell FFMA2) -----------------
__device__ __forceinline__ void fma2(ull& d, ull a, ull b) {
    asm("fma.rn.f32x2 %0, %1, %2, %3;" : "=l"(d) : "l"(a), "l"(b), "l"(d));
}
__device__ __forceinline__ ull dup2(float x) {
    ull r; asm("mov.b64 %0, {%1, %1};" : "=l"(r) : "f"(x)); return r;
}
__device__ __forceinline__ float2 unp2(ull v) {
    float2 r; asm("mov.b64 {%0, %1}, %2;" : "=f"(r.x), "=f"(r.y) : "l"(v)); return r;
}
__device__ __forceinline__ uint32_t smem_u32(const void* p) {
    uint32_t a;
    asm("{ .reg .u64 t; cvta.to.shared.u64 t, %1; cvt.u32.u64 %0, t; }" : "=r"(a) : "l"(p));
    return a;
}
__device__ __forceinline__ uint32_t mapa_u32(uint32_t addr, int rank) {
    uint32_t r;
    asm("mapa.shared::cluster.u32 %0, %1, %2;" : "=r"(r) : "r"(addr), "r"(rank));
    return r;
}

// ---------------- device scratch ---------------------------------------------
__device__ float g_xg1f[(size_t)T1 * G4H * NB];   // [t][gate_row][b]
__device__ float g_xg1b[(size_t)T1 * G4H * NB];
__device__ float g_xg2f[(size_t)T2 * G4H * NB];
__device__ float g_xg2b[(size_t)T2 * G4H * NB];
__device__ float g_out1[(size_t)NB * T1 * HDC];   // [b][t][ch]
__device__ float g_pool1[(size_t)NB * T2 * HDC];
__device__ float g_out2[(size_t)NB * T2 * HDC];

// ---------------- small helpers ---------------------------------------------
__global__ void k_zero(float* __restrict__ p, size_t n) {
    size_t i = (size_t)blockIdx.x * blockDim.x + threadIdx.x;
    size_t st = (size_t)gridDim.x * blockDim.x;
    for (; i < n; i += st) p[i] = 0.f;
}

__global__ void k_pool(const float* __restrict__ in, float* __restrict__ out) {
    size_t n = (size_t)NB * T2 * HDC;
    size_t i = (size_t)blockIdx.x * blockDim.x + threadIdx.x;
    size_t st = (size_t)gridDim.x * blockDim.x;
    for (; i < n; i += st) {
        int c  = (int)(i % HDC);
        size_t r = i / HDC;
        int tp = (int)(r % T2);
        int b  = (int)(r / T2);
        const float* p = in + ((size_t)b * T1 + 2 * (size_t)tp) * HDC + c;
        out[i] = fmaxf(p[0], p[HDC]);
    }
}

__global__ void k_lens(const int* __restrict__ xlen, float* __restrict__ out) {
    int i = threadIdx.x;
    if (i < NB) out[i] = (float)(xlen[i] >> 1);
}

// ---------------- projection / linear GEMM (R5 version — proven 310us) -------
__global__ void __launch_bounds__(128, 2) k_proj(
    const float* __restrict__ X, const float* __restrict__ W,
    const float* __restrict__ bias, float* __restrict__ out,
    int Tt, int K, long long ot, long long orr, long long ob)
{
    __shared__ __align__(16) float a_sh[16][256];
    __shared__ __align__(16) float b_sh[16][32];

    const int t    = blockIdx.y;
    const int row0 = blockIdx.x * 256;
    const int tid  = threadIdx.x;
    const int rowg = tid >> 2;
    const int colg = tid & 3;

    ull acc[4][8];
#pragma unroll
    for (int i = 0; i < 4; i++)
#pragma unroll
        for (int j = 0; j < 8; j++) acc[i][j] = 0ull;

    for (int k0 = 0; k0 < K; k0 += 16) {
        {
            const float* wp = W + (size_t)(row0 + tid) * K + k0;
            float4 v0 = ((const float4*)wp)[0];
            float4 v1 = ((const float4*)wp)[1];
            float4 v2 = ((const float4*)wp)[2];
            float4 v3 = ((const float4*)wp)[3];
            a_sh[ 0][tid] = v0.x; a_sh[ 1][tid] = v0.y; a_sh[ 2][tid] = v0.z; a_sh[ 3][tid] = v0.w;
            a_sh[ 4][tid] = v1.x; a_sh[ 5][tid] = v1.y; a_sh[ 6][tid] = v1.z; a_sh[ 7][tid] = v1.w;
            a_sh[ 8][tid] = v2.x; a_sh[ 9][tid] = v2.y; a_sh[10][tid] = v2.z; a_sh[11][tid] = v2.w;
            a_sh[12][tid] = v3.x; a_sh[13][tid] = v3.y; a_sh[14][tid] = v3.z; a_sh[15][tid] = v3.w;
            wp += (size_t)128 * K;
            v0 = ((const float4*)wp)[0];
            v1 = ((const float4*)wp)[1];
            v2 = ((const float4*)wp)[2];
            v3 = ((const float4*)wp)[3];
            const int r2 = tid + 128;
            a_sh[ 0][r2] = v0.x; a_sh[ 1][r2] = v0.y; a_sh[ 2][r2] = v0.z; a_sh[ 3][r2] = v0.w;
            a_sh[ 4][r2] = v1.x; a_sh[ 5][r2] = v1.y; a_sh[ 6][r2] = v1.z; a_sh[ 7][r2] = v1.w;
            a_sh[ 8][r2] = v2.x; a_sh[ 9][r2] = v2.y; a_sh[10][r2] = v2.z; a_sh[11][r2] = v2.w;
            a_sh[12][r2] = v3.x; a_sh[13][r2] = v3.y; a_sh[14][r2] = v3.z; a_sh[15][r2] = v3.w;
        }
        {
            const int bb = tid >> 2, ko = (tid & 3) * 4;
            const float* xp = X + ((size_t)bb * Tt + t) * K + k0 + ko;
            float4 u = *(const float4*)xp;
            b_sh[ko + 0][bb] = u.x; b_sh[ko + 1][bb] = u.y;
            b_sh[ko + 2][bb] = u.z; b_sh[ko + 3][bb] = u.w;
        }
        __syncthreads();
#pragma unroll
        for (int kk = 0; kk < 16; kk++) {
            ulonglong2 a01 = *(const ulonglong2*)&a_sh[kk][rowg * 8];
            ulonglong2 a23 = *(const ulonglong2*)&a_sh[kk][rowg * 8 + 4];
            float4 u0 = *(const float4*)&b_sh[kk][colg * 8];
            float4 u1 = *(const float4*)&b_sh[kk][colg * 8 + 4];
            ull b0 = dup2(u0.x), b1 = dup2(u0.y), b2 = dup2(u0.z), b3 = dup2(u0.w);
            ull b4 = dup2(u1.x), b5 = dup2(u1.y), b6 = dup2(u1.z), b7 = dup2(u1.w);
            fma2(acc[0][0], a01.x, b0); fma2(acc[0][1], a01.x, b1);
            fma2(acc[0][2], a01.x, b2); fma2(acc[0][3], a01.x, b3);
            fma2(acc[0][4], a01.x, b4); fma2(acc[0][5], a01.x, b5);
            fma2(acc[0][6], a01.x, b6); fma2(acc[0][7], a01.x, b7);
            fma2(acc[1][0], a01.y, b0); fma2(acc[1][1], a01.y, b1);
            fma2(acc[1][2], a01.y, b2); fma2(acc[1][3], a01.y, b3);
            fma2(acc[1][4], a01.y, b4); fma2(acc[1][5], a01.y, b5);
            fma2(acc[1][6], a01.y, b6); fma2(acc[1][7], a01.y, b7);
            fma2(acc[2][0], a23.x, b0); fma2(acc[2][1], a23.x, b1);
            fma2(acc[2][2], a23.x, b2); fma2(acc[2][3], a23.x, b3);
            fma2(acc[2][4], a23.x, b4); fma2(acc[2][5], a23.x, b5);
            fma2(acc[2][6], a23.x, b6); fma2(acc[2][7], a23.x, b7);
            fma2(acc[3][0], a23.y, b0); fma2(acc[3][1], a23.y, b1);
            fma2(acc[3][2], a23.y, b2); fma2(acc[3][3], a23.y, b3);
            fma2(acc[3][4], a23.y, b4); fma2(acc[3][5], a23.y, b5);
            fma2(acc[3][6], a23.y, b6); fma2(acc[3][7], a23.y, b7);
        }
        __syncthreads();
    }

    const int rbase = row0 + rowg * 8;
    float4 bv0 = *(const float4*)&bias[rbase];
    float4 bv1 = *(const float4*)&bias[rbase + 4];
    const float bv[8] = {bv0.x, bv0.y, bv0.z, bv0.w, bv1.x, bv1.y, bv1.z, bv1.w};

    if (ob == 1) {
        float* op = out + (size_t)t * ot + (size_t)rbase * orr + colg * 8;
#pragma unroll
        for (int rp = 0; rp < 4; rp++) {
            float va[8], vb[8];
#pragma unroll
            for (int c = 0; c < 8; c++) {
                float2 u = unp2(acc[rp][c]);
                va[c] = u.x + bv[2 * rp];
                vb[c] = u.y + bv[2 * rp + 1];
            }
            float* r0 = op + (size_t)(2 * rp) * orr;
            float* r1 = op + (size_t)(2 * rp + 1) * orr;
            *(float4*)r0       = make_float4(va[0], va[1], va[2], va[3]);
            *(float4*)(r0 + 4) = make_float4(va[4], va[5], va[6], va[7]);
            *(float4*)r1       = make_float4(vb[0], vb[1], vb[2], vb[3]);
            *(float4*)(r1 + 4) = make_float4(vb[4], vb[5], vb[6], vb[7]);
        }
    } else {
        float* op = out + (size_t)t * ot + rbase;
#pragma unroll
        for (int c = 0; c < 8; c++) {
            size_t boff = (size_t)(colg * 8 + c) * ob;
            float2 p0 = unp2(acc[0][c]);
            float2 p1 = unp2(acc[1][c]);
            float2 p2 = unp2(acc[2][c]);
            float2 p3 = unp2(acc[3][c]);
            *(float4*)(op + boff)     = make_float4(p0.x + bv[0], p0.y + bv[1], p1.x + bv[2], p1.y + bv[3]);
            *(float4*)(op + boff + 4) = make_float4(p2.x + bv[4], p2.y + bv[5], p3.x + bv[6], p3.y + bv[7]);
        }
    }
}

// ---------------- persistent recurrent LSTM: DSMEM + mbarrier sync -----------
__device__ __forceinline__ float fsig(float x) {
    return 1.f / (1.f + __expf(-x));
}
__device__ __forceinline__ float ftanh(float x) {
    float e = __expf(2.f * x);
    return 1.f - 2.f / (e + 1.f);
}

// smem: w_sh 64KB | h_sh 8KB [2][256][8] | part 9216B | stage 512B | mbar 2x8B
#define PART_STRIDE 9
#define HBUF_FLOATS (HH * 8)
#define HBUF_BYTES  (HBUF_FLOATS * 4)
#define OFF_HSH   65536
#define OFF_PART  (OFF_HSH + 2 * HBUF_BYTES)
#define OFF_STAGE (OFF_PART + 4 * 64 * PART_STRIDE * 4)
#define OFF_MBAR  (OFF_STAGE + 512)
#define LSTM_SMEM (OFF_MBAR + 64)

__global__ void __launch_bounds__(128, 1) k_lstm(
    const float* __restrict__ xgF, const float* __restrict__ xgB,
    const float* __restrict__ WhhF, const float* __restrict__ WhhB,
    const int* __restrict__ xlen, int lenShift,
    float* __restrict__ out, int Tt)
{
    extern __shared__ __align__(16) char dynsmem[];
    float* w_sh  = (float*)dynsmem;                  // [256][64]
    float* h_sh  = (float*)(dynsmem + OFF_HSH);      // [2][256][8]
    float* part  = (float*)(dynsmem + OFF_PART);     // [4][64][9]
    float* stage = (float*)(dynsmem + OFF_STAGE);    // [128]

    const int bx  = (int)blockIdx.x;
    const int dir = bx >> 6;
    const int bs  = (bx >> 4) & 3;
    const int hs  = bx & 15;           // cluster rank

    const float* xg  = dir ? xgB : xgF;
    const float* Whh = dir ? WhhB : WhhF;

    const int tid  = threadIdx.x;
    const int warp = tid >> 5, lane = tid & 31;
    const int q    = lane & 15;
    const int bg4  = lane >> 4;
    const int kbase = warp * 64;

    // zero h buffers (both parities)
    {
        float4* hz = (float4*)h_sh;
#pragma unroll
        for (int j = tid; j < 2 * HBUF_FLOATS / 4; j += 128) hz[j] = make_float4(0.f, 0.f, 0.f, 0.f);
    }

    // stage Whh slice [256 k][64 local rows]
    {
        const int r  = tid & 63;
        const int ko = (tid >> 6) * 128;
        const int grow = (r >> 4) * HH + hs * 16 + (r & 15);
        const float* wp = Whh + (size_t)grow * HH + ko;
#pragma unroll
        for (int j = 0; j < 128; j += 4) {
            float4 v = *(const float4*)(wp + j);
            w_sh[(size_t)(ko + j + 0) * 64 + r] = v.x;
            w_sh[(size_t)(ko + j + 1) * 64 + r] = v.y;
            w_sh[(size_t)(ko + j + 2) * 64 + r] = v.z;
            w_sh[(size_t)(ko + j + 3) * 64 + r] = v.w;
        }
    }

    // mbarrier init (2 phase-alternating barriers, 16 arrivals each)
    const uint32_t mbar_u32 = smem_u32(dynsmem + OFF_MBAR);
    if (tid == 0) {
        asm volatile("mbarrier.init.shared.b64 [%0], %1;" :: "r"(mbar_u32), "r"(16u) : "memory");
        asm volatile("mbarrier.init.shared.b64 [%0], %1;" :: "r"(mbar_u32 + 8), "r"(16u) : "memory");
    }

    // peer DSMEM base addresses
    const uint32_t h_u32 = smem_u32(h_sh);
    uint32_t peer_h[CLSZ], peer_m[CLSZ];
#pragma unroll
    for (int r = 0; r < CLSZ; r++) {
        peer_h[r] = mapa_u32(h_u32, r);
        peer_m[r] = mapa_u32(mbar_u32, r);
    }

    // pointwise role
    const int hl_p = tid >> 3;
    const int bl_p = tid & 7;
    const int hk   = hs * 16 + hl_p;
    const int b_g  = bs * 8 + bl_p;
    const int len_b = xlen[b_g] >> lenShift;
    int gmax = 0;
#pragma unroll
    for (int j = 0; j < 8; j++) {
        int l = xlen[bs * 8 + j] >> lenShift;
        gmax = (l > gmax) ? l : gmax;
    }
    float c_st = 0.f, h_st = 0.f;

    __syncthreads();
    // all CTAs' h buffers zeroed + mbarriers initialized before any peer ops
    asm volatile("barrier.cluster.arrive.aligned;" ::: "memory");
    asm volatile("barrier.cluster.wait.aligned;" ::: "memory");

    // gate-input prefetch for step 0
    float xg0, xg1, xg2, xg3;
    {
        int tx = dir ? (len_b - 1) : 0;
        if (tx < 0) tx = 0;
        const float* xp = xg + (size_t)tx * (G4H * NB) + (size_t)hk * NB + b_g;
        xg0 = __ldg(xp);
        xg1 = __ldg(xp + 256 * NB);
        xg2 = __ldg(xp + 512 * NB);
        xg3 = __ldg(xp + 768 * NB);
    }

    int ph[2] = {0, 0};   // per-mbar phase parity

    for (int s = 0; s < gmax; s++) {
        const int bufp = s & 1;

        // ---- wait for buffer bufp (filled by peers at step s-1) ----
        if (s > 0) {
            const uint32_t mb = mbar_u32 + (uint32_t)bufp * 8;
            const uint32_t parity = (uint32_t)ph[bufp];
            uint32_t done;
            asm volatile(
                "{\n\t.reg .pred p;\n\t"
                "mbarrier.try_wait.parity.acquire.cluster.shared::cta.b64 p, [%1], %2;\n\t"
                "selp.b32 %0, 1, 0, p;\n\t}"
                : "=r"(done) : "r"(mb), "r"(parity) : "memory");
            if (!done) {
                asm volatile(
                    "{\n\t.reg .pred P1;\n\t"
                    "WL_%=:\n\t"
                    "mbarrier.try_wait.parity.acquire.cluster.shared::cta.b64 P1, [%0], %1, 0x989680;\n\t"
                    "@P1 bra.uni WD_%=;\n\t"
                    "bra.uni WL_%=;\n\t"
                    "WD_%=:\n\t}"
                    :: "r"(mb), "r"(parity) : "memory");
            }
            ph[bufp] ^= 1;
        }

        // ---- GEMM slice from local h_sh[bufp] ----
        ull acc[2][4] = {};
        const float* wq = w_sh + (size_t)kbase * 64 + q * 4;
        const float* hq = h_sh + (size_t)bufp * HBUF_FLOATS + (size_t)kbase * 8 + bg4 * 4;
#pragma unroll 16
        for (int k = 0; k < 64; k++) {
            ulonglong2 wv = *(const ulonglong2*)(wq + (size_t)k * 64);
            float4 hv = *(const float4*)(hq + (size_t)k * 8);
            ull h0 = dup2(hv.x), h1 = dup2(hv.y), h2 = dup2(hv.z), h3 = dup2(hv.w);
            fma2(acc[0][0], wv.x, h0); fma2(acc[0][1], wv.x, h1);
            fma2(acc[0][2], wv.x, h2); fma2(acc[0][3], wv.x, h3);
            fma2(acc[1][0], wv.y, h0); fma2(acc[1][1], wv.y, h1);
            fma2(acc[1][2], wv.y, h2); fma2(acc[1][3], wv.y, h3);
        }

        // ---- partials ----
#pragma unroll
        for (int i = 0; i < 2; i++) {
#pragma unroll
            for (int j = 0; j < 4; j++) {
                float2 u = unp2(acc[i][j]);
                float* p0 = part + ((size_t)warp * 64 + q * 4 + 2 * i) * PART_STRIDE + bg4 * 4 + j;
                p0[0] = u.x;
                p0[PART_STRIDE] = u.y;
            }
        }
        __syncthreads();

        // ---- reduce + pointwise for (hl_p, bl_p) ----
        float g0 = xg0, g1 = xg1, g2 = xg2, g3 = xg3;
#pragma unroll
        for (int w = 0; w < 4; w++) {
            const float* pr = part + (size_t)w * 64 * PART_STRIDE + bl_p;
            g0 += pr[(0  + hl_p) * PART_STRIDE];
            g1 += pr[(16 + hl_p) * PART_STRIDE];
            g2 += pr[(32 + hl_p) * PART_STRIDE];
            g3 += pr[(48 + hl_p) * PART_STRIDE];
        }
        float ig = fsig(g0);
        float fg = fsig(g1);
        float gg = ftanh(g2);
        float og = fsig(g3);
        float c_n = fg * c_st + ig * gg;
        float h_n = og * ftanh(c_n);
        if (s < len_b) {
            c_st = c_n; h_st = h_n;
            int t_o = dir ? (len_b - 1 - s) : s;
            out[((size_t)b_g * Tt + t_o) * HDC + dir * HH + hk] = h_n;
        }

        if (s + 1 < gmax) {
            // ---- stage stripe, coalesced v4 DSMEM copy to all 16 ranks ----
            stage[tid] = h_st;
            __syncthreads();
            {
                const uint32_t dOff = (uint32_t)((bufp ^ 1) * HBUF_BYTES) +
                                      (uint32_t)(hs * 512) + (uint32_t)(lane * 16);
                const float4 v = *(const float4*)&stage[lane * 4];
#pragma unroll
                for (int i = 0; i < 4; i++) {
                    const int r = warp * 4 + i;
                    asm volatile("st.shared::cluster.v4.f32 [%0], {%1,%2,%3,%4};"
                                 :: "r"(peer_h[r] + dOff),
                                    "f"(v.x), "f"(v.y), "f"(v.z), "f"(v.w) : "memory");
                }
            }
            __syncthreads();
            // ---- signal: 16 parallel remote arrives on mbar[bufp^1] ----
            if (tid < CLSZ) {
                asm volatile("fence.acq_rel.cluster;" ::: "memory");
                asm volatile("mbarrier.arrive.shared::cluster.b64 _, [%0];"
                             :: "r"(peer_m[tid] + (uint32_t)((bufp ^ 1) * 8)) : "memory");
            }
            // ---- xg prefetch for step s+1 (overlaps arrive fan-out) ----
            {
                int sn = s + 1;
                int tx = dir ? (len_b - 1 - sn) : sn;
                if (tx < 0) tx = 0;
                if (tx >= Tt) tx = Tt - 1;
                const float* xp = xg + (size_t)tx * (G4H * NB) + (size_t)hk * NB + b_g;
                xg0 = __ldg(xp);
                xg1 = __ldg(xp + 256 * NB);
                xg2 = __ldg(xp + 512 * NB);
                xg3 = __ldg(xp + 768 * NB);
            }
        }
    }

    // all incoming traffic for this CTA was consumed at its final wait; the
    // last step sends nothing, so CTAs may exit independently.
}

// ---------------- host orchestration ----------------------------------------
extern "C" void kernel_launch(void* const* d_in, const int* in_sizes, int n_in,
                              void* d_out, int out_size) {
    const float* x     = (const float*)d_in[0];
    const int*   xlen  = (const int*)d_in[1];
    const float* Wih1f = (const float*)d_in[2];
    const float* Whh1f = (const float*)d_in[3];
    const float* b1f   = (const float*)d_in[4];
    const float* Wih1b = (const float*)d_in[5];
    const float* Whh1b = (const float*)d_in[6];
    const float* b1b   = (const float*)d_in[7];
    const float* Wih2f = (const float*)d_in[8];
    const float* Whh2f = (const float*)d_in[9];
    const float* b2f   = (const float*)d_in[10];
    const float* Wih2b = (const float*)d_in[11];
    const float* Whh2b = (const float*)d_in[12];
    const float* b2b   = (const float*)d_in[13];
    const float* Wlin  = (const float*)d_in[14];
    const float* blin  = (const float*)d_in[15];
    float* out = (float*)d_out;

    static bool s_attr_done = false;
    if (!s_attr_done) {
        cudaFuncSetAttribute(k_lstm, cudaFuncAttributeMaxDynamicSharedMemorySize, LSTM_SMEM);
        cudaFuncSetAttribute(k_lstm, cudaFuncAttributeNonPortableClusterSizeAllowed, 1);
        s_attr_done = true;
    }

    float *xg1f, *xg1b, *xg2f, *xg2b, *out1, *pool1, *out2;
    cudaGetSymbolAddress((void**)&xg1f,  g_xg1f);
    cudaGetSymbolAddress((void**)&xg1b,  g_xg1b);
    cudaGetSymbolAddress((void**)&xg2f,  g_xg2f);
    cudaGetSymbolAddress((void**)&xg2b,  g_xg2b);
    cudaGetSymbolAddress((void**)&out1,  g_out1);
    cudaGetSymbolAddress((void**)&pool1, g_pool1);
    cudaGetSymbolAddress((void**)&out2,  g_out2);

    const long long ot_xg = (long long)G4H * NB;
    const long long or_xg = NB;
    const long long ob_xg = 1;

    // zero masked-output buffers (graph replays must rewrite every call)
    k_zero<<<4096, 256>>>(out1, (size_t)NB * T1 * HDC);
    k_zero<<<4096, 256>>>(out2, (size_t)NB * T2 * HDC);

    // layer-1 gate projections: M=1024, N=(2000 t x 32 b), K=80
    k_proj<<<dim3(G4H / 256, T1), 128>>>(x, Wih1f, b1f, xg1f, T1, D1, ot_xg, or_xg, ob_xg);
    k_proj<<<dim3(G4H / 256, T1), 128>>>(x, Wih1b, b1b, xg1b, T1, D1, ot_xg, or_xg, ob_xg);

    // cluster launch helper
    auto launch_lstm = [&](const float* xf, const float* xb,
                           const float* wf, const float* wb,
                           int shift, float* o, int Tt) {
        cudaLaunchConfig_t cfg = {};
        cfg.gridDim  = dim3(128, 1, 1);
        cfg.blockDim = dim3(128, 1, 1);
        cfg.dynamicSmemBytes = LSTM_SMEM;
        cfg.stream = 0;
        cudaLaunchAttribute attrs[1];
        attrs[0].id = cudaLaunchAttributeClusterDimension;
        attrs[0].val.clusterDim.x = CLSZ;
        attrs[0].val.clusterDim.y = 1;
        attrs[0].val.clusterDim.z = 1;
        cfg.attrs = attrs;
        cfg.numAttrs = 1;
        cudaLaunchKernelEx(&cfg, k_lstm, xf, xb, wf, wb, xlen, shift, o, Tt);
    };

    // layer-1 recurrence
    launch_lstm(xg1f, xg1b, Whh1f, Whh1b, 0, out1, T1);

    // max-pool stride 2
    k_pool<<<2048, 256>>>(out1, pool1);

    // layer-2 gate projections: M=1024, K=512
    k_proj<<<dim3(G4H / 256, T2), 128>>>(pool1, Wih2f, b2f, xg2f, T2, HDC, ot_xg, or_xg, ob_xg);
    k_proj<<<dim3(G4H / 256, T2), 128>>>(pool1, Wih2b, b2b, xg2b, T2, HDC, ot_xg, or_xg, ob_xg);

    // layer-2 recurrence (lengths = x_len >> 1)
    launch_lstm(xg2f, xg2b, Whh2f, Whh2b, 1, out2, T2);

    // final linear: out[b][t][o] -> M=512, K=512, store-along-row mode
    k_proj<<<dim3(OUTC / 256, T2), 128>>>(out2, Wlin, blin, out, T2, HDC,
                                          (long long)OUTC, 1LL, (long long)T2 * OUTC);

    // lens = x_len // 2 appended as float
    if (out_size > NB * T2 * OUTC) {
        k_lens<<<1, 32>>>(xlen, out + (size_t)NB * T2 * OUTC);
    }
}

// round 12
// speedup vs baseline: 1.1347x; 1.1280x over previous
#include <cuda_runtime.h>
#include <cuda_bf16.h>
#include <cstdint>
#include <cstddef>
#include <math.h>

#define NB   32      // batch
#define T1   2000
#define T2   1000
#define D1   80
#define HH   256     // hidden per direction
#define G4H  1024    // 4*H gate rows
#define HDC  512
#define OUTC 512
#define CLSZ 16      // cluster size = blocks per group (h-shards)

typedef unsigned long long ull;

// ---------------- f32x2 packed-FMA helpers (Blackwell FFMA2) -----------------
__device__ __forceinline__ void fma2(ull& d, ull a, ull b) {
    asm("fma.rn.f32x2 %0, %1, %2, %3;" : "=l"(d) : "l"(a), "l"(b), "l"(d));
}
__device__ __forceinline__ ull dup2(float x) {
    ull r; asm("mov.b64 %0, {%1, %1};" : "=l"(r) : "f"(x)); return r;
}
__device__ __forceinline__ float2 unp2(ull v) {
    float2 r; asm("mov.b64 {%0, %1}, %2;" : "=f"(r.x), "=f"(r.y) : "l"(v)); return r;
}
__device__ __forceinline__ uint32_t smem_u32(const void* p) {
    uint32_t a;
    asm("{ .reg .u64 t; cvta.to.shared.u64 t, %1; cvt.u32.u64 %0, t; }" : "=r"(a) : "l"(p));
    return a;
}
__device__ __forceinline__ uint32_t mapa_u32(uint32_t addr, int rank) {
    uint32_t r;
    asm("mapa.shared::cluster.u32 %0, %1, %2;" : "=r"(r) : "r"(addr), "r"(rank));
    return r;
}

// ---------------- device scratch ---------------------------------------------
__device__ float g_xg1f[(size_t)T1 * G4H * NB];   // [t][gate_row][b]
__device__ float g_xg1b[(size_t)T1 * G4H * NB];
__device__ float g_xg2f[(size_t)T2 * G4H * NB];
__device__ float g_xg2b[(size_t)T2 * G4H * NB];
__device__ float g_out1[(size_t)NB * T1 * HDC];   // [b][t][ch]
__device__ float g_pool1[(size_t)NB * T2 * HDC];
__device__ float g_out2[(size_t)NB * T2 * HDC];

// ---------------- small helpers ---------------------------------------------
__global__ void k_zero(float* __restrict__ p, size_t n) {
    size_t i = (size_t)blockIdx.x * blockDim.x + threadIdx.x;
    size_t st = (size_t)gridDim.x * blockDim.x;
    for (; i < n; i += st) p[i] = 0.f;
}

__global__ void k_pool(const float* __restrict__ in, float* __restrict__ out) {
    size_t n = (size_t)NB * T2 * HDC;
    size_t i = (size_t)blockIdx.x * blockDim.x + threadIdx.x;
    size_t st = (size_t)gridDim.x * blockDim.x;
    for (; i < n; i += st) {
        int c  = (int)(i % HDC);
        size_t r = i / HDC;
        int tp = (int)(r % T2);
        int b  = (int)(r / T2);
        const float* p = in + ((size_t)b * T1 + 2 * (size_t)tp) * HDC + c;
        out[i] = fmaxf(p[0], p[HDC]);
    }
}

__global__ void k_lens(const int* __restrict__ xlen, float* __restrict__ out) {
    int i = threadIdx.x;
    if (i < NB) out[i] = (float)(xlen[i] >> 1);
}

// ---------------- projection / linear GEMM (R5 version — proven 310us) -------
__global__ void __launch_bounds__(128, 2) k_proj(
    const float* __restrict__ X, const float* __restrict__ W,
    const float* __restrict__ bias, float* __restrict__ out,
    int Tt, int K, long long ot, long long orr, long long ob)
{
    __shared__ __align__(16) float a_sh[16][256];
    __shared__ __align__(16) float b_sh[16][32];

    const int t    = blockIdx.y;
    const int row0 = blockIdx.x * 256;
    const int tid  = threadIdx.x;
    const int rowg = tid >> 2;
    const int colg = tid & 3;

    ull acc[4][8];
#pragma unroll
    for (int i = 0; i < 4; i++)
#pragma unroll
        for (int j = 0; j < 8; j++) acc[i][j] = 0ull;

    for (int k0 = 0; k0 < K; k0 += 16) {
        {
            const float* wp = W + (size_t)(row0 + tid) * K + k0;
            float4 v0 = ((const float4*)wp)[0];
            float4 v1 = ((const float4*)wp)[1];
            float4 v2 = ((const float4*)wp)[2];
            float4 v3 = ((const float4*)wp)[3];
            a_sh[ 0][tid] = v0.x; a_sh[ 1][tid] = v0.y; a_sh[ 2][tid] = v0.z; a_sh[ 3][tid] = v0.w;
            a_sh[ 4][tid] = v1.x; a_sh[ 5][tid] = v1.y; a_sh[ 6][tid] = v1.z; a_sh[ 7][tid] = v1.w;
            a_sh[ 8][tid] = v2.x; a_sh[ 9][tid] = v2.y; a_sh[10][tid] = v2.z; a_sh[11][tid] = v2.w;
            a_sh[12][tid] = v3.x; a_sh[13][tid] = v3.y; a_sh[14][tid] = v3.z; a_sh[15][tid] = v3.w;
            wp += (size_t)128 * K;
            v0 = ((const float4*)wp)[0];
            v1 = ((const float4*)wp)[1];
            v2 = ((const float4*)wp)[2];
            v3 = ((const float4*)wp)[3];
            const int r2 = tid + 128;
            a_sh[ 0][r2] = v0.x; a_sh[ 1][r2] = v0.y; a_sh[ 2][r2] = v0.z; a_sh[ 3][r2] = v0.w;
            a_sh[ 4][r2] = v1.x; a_sh[ 5][r2] = v1.y; a_sh[ 6][r2] = v1.z; a_sh[ 7][r2] = v1.w;
            a_sh[ 8][r2] = v2.x; a_sh[ 9][r2] = v2.y; a_sh[10][r2] = v2.z; a_sh[11][r2] = v2.w;
            a_sh[12][r2] = v3.x; a_sh[13][r2] = v3.y; a_sh[14][r2] = v3.z; a_sh[15][r2] = v3.w;
        }
        {
            const int bb = tid >> 2, ko = (tid & 3) * 4;
            const float* xp = X + ((size_t)bb * Tt + t) * K + k0 + ko;
            float4 u = *(const float4*)xp;
            b_sh[ko + 0][bb] = u.x; b_sh[ko + 1][bb] = u.y;
            b_sh[ko + 2][bb] = u.z; b_sh[ko + 3][bb] = u.w;
        }
        __syncthreads();
#pragma unroll
        for (int kk = 0; kk < 16; kk++) {
            ulonglong2 a01 = *(const ulonglong2*)&a_sh[kk][rowg * 8];
            ulonglong2 a23 = *(const ulonglong2*)&a_sh[kk][rowg * 8 + 4];
            float4 u0 = *(const float4*)&b_sh[kk][colg * 8];
            float4 u1 = *(const float4*)&b_sh[kk][colg * 8 + 4];
            ull b0 = dup2(u0.x), b1 = dup2(u0.y), b2 = dup2(u0.z), b3 = dup2(u0.w);
            ull b4 = dup2(u1.x), b5 = dup2(u1.y), b6 = dup2(u1.z), b7 = dup2(u1.w);
            fma2(acc[0][0], a01.x, b0); fma2(acc[0][1], a01.x, b1);
            fma2(acc[0][2], a01.x, b2); fma2(acc[0][3], a01.x, b3);
            fma2(acc[0][4], a01.x, b4); fma2(acc[0][5], a01.x, b5);
            fma2(acc[0][6], a01.x, b6); fma2(acc[0][7], a01.x, b7);
            fma2(acc[1][0], a01.y, b0); fma2(acc[1][1], a01.y, b1);
            fma2(acc[1][2], a01.y, b2); fma2(acc[1][3], a01.y, b3);
            fma2(acc[1][4], a01.y, b4); fma2(acc[1][5], a01.y, b5);
            fma2(acc[1][6], a01.y, b6); fma2(acc[1][7], a01.y, b7);
            fma2(acc[2][0], a23.x, b0); fma2(acc[2][1], a23.x, b1);
            fma2(acc[2][2], a23.x, b2); fma2(acc[2][3], a23.x, b3);
            fma2(acc[2][4], a23.x, b4); fma2(acc[2][5], a23.x, b5);
            fma2(acc[2][6], a23.x, b6); fma2(acc[2][7], a23.x, b7);
            fma2(acc[3][0], a23.y, b0); fma2(acc[3][1], a23.y, b1);
            fma2(acc[3][2], a23.y, b2); fma2(acc[3][3], a23.y, b3);
            fma2(acc[3][4], a23.y, b4); fma2(acc[3][5], a23.y, b5);
            fma2(acc[3][6], a23.y, b6); fma2(acc[3][7], a23.y, b7);
        }
        __syncthreads();
    }

    const int rbase = row0 + rowg * 8;
    float4 bv0 = *(const float4*)&bias[rbase];
    float4 bv1 = *(const float4*)&bias[rbase + 4];
    const float bv[8] = {bv0.x, bv0.y, bv0.z, bv0.w, bv1.x, bv1.y, bv1.z, bv1.w};

    if (ob == 1) {
        float* op = out + (size_t)t * ot + (size_t)rbase * orr + colg * 8;
#pragma unroll
        for (int rp = 0; rp < 4; rp++) {
            float va[8], vb[8];
#pragma unroll
            for (int c = 0; c < 8; c++) {
                float2 u = unp2(acc[rp][c]);
                va[c] = u.x + bv[2 * rp];
                vb[c] = u.y + bv[2 * rp + 1];
            }
            float* r0 = op + (size_t)(2 * rp) * orr;
            float* r1 = op + (size_t)(2 * rp + 1) * orr;
            *(float4*)r0       = make_float4(va[0], va[1], va[2], va[3]);
            *(float4*)(r0 + 4) = make_float4(va[4], va[5], va[6], va[7]);
            *(float4*)r1       = make_float4(vb[0], vb[1], vb[2], vb[3]);
            *(float4*)(r1 + 4) = make_float4(vb[4], vb[5], vb[6], vb[7]);
        }
    } else {
        float* op = out + (size_t)t * ot + rbase;
#pragma unroll
        for (int c = 0; c < 8; c++) {
            size_t boff = (size_t)(colg * 8 + c) * ob;
            float2 p0 = unp2(acc[0][c]);
            float2 p1 = unp2(acc[1][c]);
            float2 p2 = unp2(acc[2][c]);
            float2 p3 = unp2(acc[3][c]);
            *(float4*)(op + boff)     = make_float4(p0.x + bv[0], p0.y + bv[1], p1.x + bv[2], p1.y + bv[3]);
            *(float4*)(op + boff + 4) = make_float4(p2.x + bv[4], p2.y + bv[5], p3.x + bv[6], p3.y + bv[7]);
        }
    }
}

// ---------------- persistent recurrent LSTM: DSMEM clusters, 256 threads -----
__device__ __forceinline__ float fsig(float x) {
    return 1.f / (1.f + __expf(-x));
}
__device__ __forceinline__ float ftanh(float x) {
    float e = __expf(2.f * x);
    return 1.f - 2.f / (e + 1.f);
}

// smem: w_sh 64KB [256][64] | h_sh 16KB [2][256][8] | part [8][64][9]
#define PART_STRIDE 9
#define HBUF_FLOATS (HH * 8)
#define HBUF_BYTES  (HBUF_FLOATS * 4)
#define OFF_HSH   65536
#define OFF_PART  (OFF_HSH + 2 * HBUF_BYTES)
#define LSTM_SMEM (OFF_PART + 8 * 64 * PART_STRIDE * 4)

__global__ void __launch_bounds__(256, 1) k_lstm(
    const float* __restrict__ xgF, const float* __restrict__ xgB,
    const float* __restrict__ WhhF, const float* __restrict__ WhhB,
    const int* __restrict__ xlen, int lenShift,
    float* __restrict__ out, int Tt)
{
    extern __shared__ __align__(16) char dynsmem[];
    float* w_sh = (float*)dynsmem;                   // [256][64]
    float* h_sh = (float*)(dynsmem + OFF_HSH);       // [2][256][8]
    float* part = (float*)(dynsmem + OFF_PART);      // [8][64][9]

    const int bx  = (int)blockIdx.x;
    const int dir = bx >> 6;
    const int bs  = (bx >> 4) & 3;
    const int hs  = bx & 15;           // cluster rank

    const float* xg  = dir ? xgB : xgF;
    const float* Whh = dir ? WhhB : WhhF;

    const int tid  = threadIdx.x;
    const int warp = tid >> 5, lane = tid & 31;
    const int q    = lane & 15;        // row quad (4 rows = 2 f32x2 pairs)
    const int bg4  = lane >> 4;        // batch group of 4 (0,1)
    const int kbase = warp * 32;       // 32 k per warp (8 warps)

    // ---- zero h buffers (both parities) ----
    {
        float4* hz = (float4*)h_sh;
        for (int j = tid; j < 2 * HBUF_FLOATS / 4; j += 256)
            hz[j] = make_float4(0.f, 0.f, 0.f, 0.f);
    }

    // ---- stage Whh slice [256 k][64 local rows] ----
    {
        const int r  = tid & 63;
        const int ko = (tid >> 6) * 64;    // 4 groups x 64 k
        const int grow = (r >> 4) * HH + hs * 16 + (r & 15);
        const float* wp = Whh + (size_t)grow * HH + ko;
#pragma unroll
        for (int j = 0; j < 64; j += 4) {
            float4 v = *(const float4*)(wp + j);
            w_sh[(size_t)(ko + j + 0) * 64 + r] = v.x;
            w_sh[(size_t)(ko + j + 1) * 64 + r] = v.y;
            w_sh[(size_t)(ko + j + 2) * 64 + r] = v.z;
            w_sh[(size_t)(ko + j + 3) * 64 + r] = v.w;
        }
    }

    // ---- peer DSMEM addresses for the h scatter (threads 0-127 own values) --
    const uint32_t h_u32 = smem_u32(h_sh);
    uint32_t peer[CLSZ];
#pragma unroll
    for (int r = 0; r < CLSZ; r++) peer[r] = mapa_u32(h_u32, r);
    const uint32_t selfOff = ((uint32_t)(hs * 128 + tid)) * 4u;   // valid for tid<128

    // ---- pointwise role (threads 0-127) ----
    const int hl_p = (tid >> 3) & 15;
    const int bl_p = tid & 7;
    const int hk   = hs * 16 + hl_p;
    const int b_g  = bs * 8 + bl_p;
    const int len_b = xlen[b_g] >> lenShift;
    int gmax = 0;
#pragma unroll
    for (int j = 0; j < 8; j++) {
        int l = xlen[bs * 8 + j] >> lenShift;
        gmax = (l > gmax) ? l : gmax;
    }
    float c_st = 0.f, h_st = 0.f;

    __syncthreads();
    // all CTAs' h buffers zeroed before any peer writes
    asm volatile("barrier.cluster.arrive.aligned;" ::: "memory");
    asm volatile("barrier.cluster.wait.aligned;" ::: "memory");

    // gate-input prefetch for step 0 (owner threads only)
    float xg0 = 0.f, xg1 = 0.f, xg2 = 0.f, xg3 = 0.f;
    if (tid < 128) {
        int tx = dir ? (len_b - 1) : 0;
        if (tx < 0) tx = 0;
        const float* xp = xg + (size_t)tx * (G4H * NB) + (size_t)hk * NB + b_g;
        xg0 = __ldg(xp);
        xg1 = __ldg(xp + 256 * NB);
        xg2 = __ldg(xp + 512 * NB);
        xg3 = __ldg(xp + 768 * NB);
    }

    for (int s = 0; s < gmax; s++) {
        const int bufp = s & 1;

        // ---- GEMM slice from local h_sh[bufp]: 8 warps x 32 k ----
        ull acc[2][4] = {};
        const float* wq = w_sh + (size_t)kbase * 64 + q * 4;
        const float* hq = h_sh + (size_t)bufp * HBUF_FLOATS + (size_t)kbase * 8 + bg4 * 4;
#pragma unroll 16
        for (int k = 0; k < 32; k++) {
            ulonglong2 wv = *(const ulonglong2*)(wq + (size_t)k * 64);
            float4 hv = *(const float4*)(hq + (size_t)k * 8);
            ull h0 = dup2(hv.x), h1 = dup2(hv.y), h2 = dup2(hv.z), h3 = dup2(hv.w);
            fma2(acc[0][0], wv.x, h0); fma2(acc[0][1], wv.x, h1);
            fma2(acc[0][2], wv.x, h2); fma2(acc[0][3], wv.x, h3);
            fma2(acc[1][0], wv.y, h0); fma2(acc[1][1], wv.y, h1);
            fma2(acc[1][2], wv.y, h2); fma2(acc[1][3], wv.y, h3);
        }

        // ---- partials: part[warp][row(64)][b(8)] stride 9 ----
#pragma unroll
        for (int i = 0; i < 2; i++) {
#pragma unroll
            for (int j = 0; j < 4; j++) {
                float2 u = unp2(acc[i][j]);
                float* p0 = part + ((size_t)warp * 64 + q * 4 + 2 * i) * PART_STRIDE + bg4 * 4 + j;
                p0[0] = u.x;
                p0[PART_STRIDE] = u.y;
            }
        }
        __syncthreads();

        if (tid < 128) {
            // ---- reduce over 8 warps + pointwise for (hl_p, bl_p) ----
            float g0 = xg0, g1 = xg1, g2 = xg2, g3 = xg3;
#pragma unroll
            for (int w = 0; w < 8; w++) {
                const float* pr = part + (size_t)w * 64 * PART_STRIDE + bl_p;
                g0 += pr[(0  + hl_p) * PART_STRIDE];
                g1 += pr[(16 + hl_p) * PART_STRIDE];
                g2 += pr[(32 + hl_p) * PART_STRIDE];
                g3 += pr[(48 + hl_p) * PART_STRIDE];
            }
            float ig = fsig(g0);
            float fg = fsig(g1);
            float gg = ftanh(g2);
            float og = fsig(g3);
            float c_n = fg * c_st + ig * gg;
            float h_n = og * ftanh(c_n);
            if (s < len_b) {
                c_st = c_n; h_st = h_n;
                int t_o = dir ? (len_b - 1 - s) : s;
                out[((size_t)b_g * Tt + t_o) * HDC + dir * HH + hk] = h_n;
            }

            // ---- scatter h to all 16 CTAs' h_sh[bufp^1] via DSMEM ----
            const uint32_t off = (uint32_t)((bufp ^ 1) * HBUF_BYTES) + selfOff;
            const float hv = h_st;
#pragma unroll
            for (int r = 0; r < CLSZ; r++) {
                asm volatile("st.shared::cluster.f32 [%0], %1;"
                             :: "r"(peer[r] + off), "f"(hv) : "memory");
            }
        }

        // release my stores; overlap xg prefetch with peers finishing
        asm volatile("barrier.cluster.arrive.aligned;" ::: "memory");
        if (tid < 128) {
            int sn = s + 1;
            int tx = dir ? (len_b - 1 - sn) : sn;
            if (tx < 0) tx = 0;
            if (tx >= Tt) tx = Tt - 1;
            const float* xp = xg + (size_t)tx * (G4H * NB) + (size_t)hk * NB + b_g;
            xg0 = __ldg(xp);
            xg1 = __ldg(xp + 256 * NB);
            xg2 = __ldg(xp + 512 * NB);
            xg3 = __ldg(xp + 768 * NB);
        }
        asm volatile("barrier.cluster.wait.aligned;" ::: "memory");
    }
}

// ---------------- host orchestration ----------------------------------------
extern "C" void kernel_launch(void* const* d_in, const int* in_sizes, int n_in,
                              void* d_out, int out_size) {
    const float* x     = (const float*)d_in[0];
    const int*   xlen  = (const int*)d_in[1];
    const float* Wih1f = (const float*)d_in[2];
    const float* Whh1f = (const float*)d_in[3];
    const float* b1f   = (const float*)d_in[4];
    const float* Wih1b = (const float*)d_in[5];
    const float* Whh1b = (const float*)d_in[6];
    const float* b1b   = (const float*)d_in[7];
    const float* Wih2f = (const float*)d_in[8];
    const float* Whh2f = (const float*)d_in[9];
    const float* b2f   = (const float*)d_in[10];
    const float* Wih2b = (const float*)d_in[11];
    const float* Whh2b = (const float*)d_in[12];
    const float* b2b   = (const float*)d_in[13];
    const float* Wlin  = (const float*)d_in[14];
    const float* blin  = (const float*)d_in[15];
    float* out = (float*)d_out;

    static bool s_attr_done = false;
    if (!s_attr_done) {
        cudaFuncSetAttribute(k_lstm, cudaFuncAttributeMaxDynamicSharedMemorySize, LSTM_SMEM);
        cudaFuncSetAttribute(k_lstm, cudaFuncAttributeNonPortableClusterSizeAllowed, 1);
        s_attr_done = true;
    }

    float *xg1f, *xg1b, *xg2f, *xg2b, *out1, *pool1, *out2;
    cudaGetSymbolAddress((void**)&xg1f,  g_xg1f);
    cudaGetSymbolAddress((void**)&xg1b,  g_xg1b);
    cudaGetSymbolAddress((void**)&xg2f,  g_xg2f);
    cudaGetSymbolAddress((void**)&xg2b,  g_xg2b);
    cudaGetSymbolAddress((void**)&out1,  g_out1);
    cudaGetSymbolAddress((void**)&pool1, g_pool1);
    cudaGetSymbolAddress((void**)&out2,  g_out2);

    const long long ot_xg = (long long)G4H * NB;
    const long long or_xg = NB;
    const long long ob_xg = 1;

    // zero masked-output buffers (graph replays must rewrite every call)
    k_zero<<<4096, 256>>>(out1, (size_t)NB * T1 * HDC);
    k_zero<<<4096, 256>>>(out2, (size_t)NB * T2 * HDC);

    // layer-1 gate projections: M=1024, N=(2000 t x 32 b), K=80
    k_proj<<<dim3(G4H / 256, T1), 128>>>(x, Wih1f, b1f, xg1f, T1, D1, ot_xg, or_xg, ob_xg);
    k_proj<<<dim3(G4H / 256, T1), 128>>>(x, Wih1b, b1b, xg1b, T1, D1, ot_xg, or_xg, ob_xg);

    // cluster launch helper
    auto launch_lstm = [&](const float* xf, const float* xb,
                           const float* wf, const float* wb,
                           int shift, float* o, int Tt) {
        cudaLaunchConfig_t cfg = {};
        cfg.gridDim  = dim3(128, 1, 1);
        cfg.blockDim = dim3(256, 1, 1);
        cfg.dynamicSmemBytes = LSTM_SMEM;
        cfg.stream = 0;
        cudaLaunchAttribute attrs[1];
        attrs[0].id = cudaLaunchAttributeClusterDimension;
        attrs[0].val.clusterDim.x = CLSZ;
        attrs[0].val.clusterDim.y = 1;
        attrs[0].val.clusterDim.z = 1;
        cfg.attrs = attrs;
        cfg.numAttrs = 1;
        cudaLaunchKernelEx(&cfg, k_lstm, xf, xb, wf, wb, xlen, shift, o, Tt);
    };

    // layer-1 recurrence
    launch_lstm(xg1f, xg1b, Whh1f, Whh1b, 0, out1, T1);

    // max-pool stride 2
    k_pool<<<2048, 256>>>(out1, pool1);

    // layer-2 gate projections: M=1024, K=512
    k_proj<<<dim3(G4H / 256, T2), 128>>>(pool1, Wih2f, b2f, xg2f, T2, HDC, ot_xg, or_xg, ob_xg);
    k_proj<<<dim3(G4H / 256, T2), 128>>>(pool1, Wih2b, b2b, xg2b, T2, HDC, ot_xg, or_xg, ob_xg);

    // layer-2 recurrence (lengths = x_len >> 1)
    launch_lstm(xg2f, xg2b, Whh2f, Whh2b, 1, out2, T2);

    // final linear: out[b][t][o] -> M=512, K=512, store-along-row mode
    k_proj<<<dim3(OUTC / 256, T2), 128>>>(out2, Wlin, blin, out, T2, HDC,
                                          (long long)OUTC, 1LL, (long long)T2 * OUTC);

    // lens = x_len // 2 appended as float
    if (out_size > NB * T2 * OUTC) {
        k_lens<<<1, 32>>>(xlen, out + (size_t)NB * T2 * OUTC);
    }
}